// round 3
// baseline (speedup 1.0000x reference)
#include <cuda_runtime.h>
#include <cstddef>

// Problem shape (fixed by the dataset)
constexpr int B = 8;
constexpr int T = 2048;
constexpr int C = 4096;
constexpr int U = 200;

constexpr float NEGF = -1e30f;

// Scratch (no cudaMalloc allowed): per-(b,t) target log-probs and per-batch results
__device__ float g_lpt[(size_t)B * T * U];   // 13.1 MB
__device__ float g_partial[B];

// ---------------------------------------------------------------------------
// Kernel 1: one block per (b,t) row of C=4096 floats.
//   - stream row into SMEM (and registers) with float4 loads
//   - block-reduce max, then sum of exp(x-max) -> lse
//   - gather the 200 target logits from SMEM, write lpt = x[tgt] - lse
// HBM-bound: 268 MB read total.
// ---------------------------------------------------------------------------
__global__ __launch_bounds__(256) void lse_gather_kernel(
    const float* __restrict__ x, const int* __restrict__ tgt)
{
    const int row = blockIdx.x;          // b*T + t
    const int b   = row >> 11;           // T = 2048
    const int tid = threadIdx.x;

    __shared__ float sh[C];              // 16 KB row stage for the gather
    __shared__ float red[8];
    __shared__ float s_bcast;

    const float4* r4 = reinterpret_cast<const float4*>(x) + (size_t)row * (C / 4);

    float4 v[4];
    float mx = -3.402823466e38f;
#pragma unroll
    for (int i = 0; i < 4; i++) {
        v[i] = r4[tid + i * 256];
        reinterpret_cast<float4*>(sh)[tid + i * 256] = v[i];
        mx = fmaxf(mx, fmaxf(fmaxf(v[i].x, v[i].y), fmaxf(v[i].z, v[i].w)));
    }

    // block max
#pragma unroll
    for (int o = 16; o; o >>= 1) mx = fmaxf(mx, __shfl_xor_sync(0xffffffffu, mx, o));
    if ((tid & 31) == 0) red[tid >> 5] = mx;
    __syncthreads();
    if (tid == 0) {
        float m = red[0];
#pragma unroll
        for (int w = 1; w < 8; w++) m = fmaxf(m, red[w]);
        s_bcast = m;
    }
    __syncthreads();
    mx = s_bcast;

    // block sum of exp(x - max)
    float s = 0.f;
#pragma unroll
    for (int i = 0; i < 4; i++) {
        s += __expf(v[i].x - mx) + __expf(v[i].y - mx)
           + __expf(v[i].z - mx) + __expf(v[i].w - mx);
    }
#pragma unroll
    for (int o = 16; o; o >>= 1) s += __shfl_xor_sync(0xffffffffu, s, o);
    __syncthreads();                     // protect red[] reuse
    if ((tid & 31) == 0) red[tid >> 5] = s;
    __syncthreads();
    if (tid == 0) {
        float t = 0.f;
#pragma unroll
        for (int w = 0; w < 8; w++) t += red[w];
        s_bcast = mx + __logf(t);
    }
    __syncthreads();
    const float lse = s_bcast;

    // gather 200 target logits from the SMEM-staged row.
    // targets are int32 (JAX x64-disabled downcasts the reference's int64).
    // '& (C-1)' is a free hard bound so this LDS can never trap.
    if (tid < U) {
        const int c = tgt[b * U + tid] & (C - 1);
        g_lpt[(size_t)row * U + tid] = sh[c] - lse;
    }
}

// ---------------------------------------------------------------------------
// Kernel 2: alpha recursion. One block per batch, one thread per u.
//   alpha[t,u] = lpt[t,u] + logaddexp(alpha[t-1,u], alpha[t-1,u-1])
// Double-buffered SMEM neighbor exchange -> exactly one __syncthreads per t.
// Fast-math logaddexp: m + log(1 + exp(-|d|)); exact for the -1e30 sentinel
// (exp(-2e30) flushes to 0, log(1) = 0).
// 224 threads = 7 warps (>= U=200): fewer warps -> cheaper barrier release.
// ---------------------------------------------------------------------------
__global__ __launch_bounds__(224) void alpha_kernel()
{
    const int b = blockIdx.x;
    const int u = threadIdx.x;           // u < 200 are real lattice columns

    __shared__ float buf[2][225];

    const float* __restrict__ lp = g_lpt + (size_t)b * T * U + u;

    float alpha = (u == 0) ? lp[0] : NEGF;

    // prefetch t = 1
    float p_next = (u < U) ? lp[U] : 0.f;
    lp += 2 * U;                          // points at t = 2 entry

    for (int t = 1; t < T; t++) {
        const float p = p_next;
        if (t + 1 < T) {
            p_next = (u < U) ? *lp : 0.f;
            lp += U;
        }

        const int s = t & 1;
        buf[s][u] = alpha;
        __syncthreads();
        const float left = (u == 0) ? NEGF : buf[s][u - 1];

        const float m = fmaxf(alpha, left);
        const float d = fabsf(alpha - left);
        alpha = p + m + __logf(1.f + __expf(-d));
    }

    if (u == U - 1) g_partial[b] = alpha;
}

// ---------------------------------------------------------------------------
// Kernel 3: deterministic final reduction into the scalar output.
// ---------------------------------------------------------------------------
__global__ void finalize_kernel(float* __restrict__ out)
{
    float s = 0.f;
#pragma unroll
    for (int b = 0; b < B; b++) s += g_partial[b];
    out[0] = -s / (float)B;
}

extern "C" void kernel_launch(void* const* d_in, const int* in_sizes, int n_in,
                              void* d_out, int out_size)
{
    const float* x   = (const float*)d_in[0];   // [B, T, C] fp32
    const int*   tgt = (const int*)d_in[1];     // [B, U] int32 (see note above)
    float*       out = (float*)d_out;           // scalar fp32

    lse_gather_kernel<<<B * T, 256>>>(x, tgt);
    alpha_kernel<<<B, 224>>>();
    finalize_kernel<<<1, 1>>>(out);
}

// round 5
// speedup vs baseline: 2.9057x; 2.9057x over previous
#include <cuda_runtime.h>
#include <cstddef>
#include <cstdint>

// Problem shape (fixed by the dataset)
constexpr int B = 8;
constexpr int T = 2048;
constexpr int C = 4096;
constexpr int U = 200;

constexpr float NEGF = -1e30f;

// Scratch (no cudaMalloc allowed)
__device__ float g_lpt[(size_t)B * T * U];   // 13.1 MB
__device__ float g_partial[B];

// ---------------------------------------------------------------------------
// Kernel 1: unchanged (measured at DRAM roofline: 47.5us, 72% DRAM).
// ---------------------------------------------------------------------------
__global__ __launch_bounds__(256) void lse_gather_kernel(
    const float* __restrict__ x, const int* __restrict__ tgt)
{
    const int row = blockIdx.x;          // b*T + t
    const int b   = row >> 11;           // T = 2048
    const int tid = threadIdx.x;

    __shared__ float sh[C];
    __shared__ float red[8];
    __shared__ float s_bcast;

    const float4* r4 = reinterpret_cast<const float4*>(x) + (size_t)row * (C / 4);

    float4 v[4];
    float mx = -3.402823466e38f;
#pragma unroll
    for (int i = 0; i < 4; i++) {
        v[i] = r4[tid + i * 256];
        reinterpret_cast<float4*>(sh)[tid + i * 256] = v[i];
        mx = fmaxf(mx, fmaxf(fmaxf(v[i].x, v[i].y), fmaxf(v[i].z, v[i].w)));
    }

#pragma unroll
    for (int o = 16; o; o >>= 1) mx = fmaxf(mx, __shfl_xor_sync(0xffffffffu, mx, o));
    if ((tid & 31) == 0) red[tid >> 5] = mx;
    __syncthreads();
    if (tid == 0) {
        float m = red[0];
#pragma unroll
        for (int w = 1; w < 8; w++) m = fmaxf(m, red[w]);
        s_bcast = m;
    }
    __syncthreads();
    mx = s_bcast;

    float s = 0.f;
#pragma unroll
    for (int i = 0; i < 4; i++) {
        s += __expf(v[i].x - mx) + __expf(v[i].y - mx)
           + __expf(v[i].z - mx) + __expf(v[i].w - mx);
    }
#pragma unroll
    for (int o = 16; o; o >>= 1) s += __shfl_xor_sync(0xffffffffu, s, o);
    __syncthreads();
    if ((tid & 31) == 0) red[tid >> 5] = s;
    __syncthreads();
    if (tid == 0) {
        float t = 0.f;
#pragma unroll
        for (int w = 0; w < 8; w++) t += red[w];
        s_bcast = mx + __logf(t);
    }
    __syncthreads();
    const float lse = s_bcast;

    if (tid < U) {
        const int c = tgt[b * U + tid] & (C - 1);
        g_lpt[(size_t)row * U + tid] = sh[c] - lse;
    }
}

// ---------------------------------------------------------------------------
// Kernel 2 v2: single-warp-per-batch alpha recursion.
//   - lane owns 7 contiguous u columns (32*7 = 224 >= 200)
//   - only cross-lane dep is one __shfl_up of the boundary alpha per step
//   - lpt staged into SMEM in 16-step chunks via double-buffered cp.async
//     (prefetch a full chunk ahead -> no DRAM latency on the serial chain)
//   - logaddexp tail f(d) = log1p(exp(-d)) via 256-entry slope/intercept LUT
//     (no MUFU in the steady-state loop; interp err <= 1.2e-4 per step)
// Columns u >= 200 compute junk; junk flows only upward in u and can never
// reach the u=199 output. fmaxf/fminf absorb NaN, so even NaN junk stays
// confined and finite-indexed.
// ---------------------------------------------------------------------------
constexpr int TS   = 16;          // time steps per staged chunk
constexpr int NCH  = T / TS;      // 128 chunks
constexpr int BUFN = TS * U + 32; // +32 floats pad for u in [200,224) overreads
constexpr int LUTN = 256;
constexpr float LUT_SCALE = 16.0f;   // LUT entries per unit of d, covers [0,16)

__device__ __forceinline__ void cp_chunk(float* dst_sh, const float* src_g, int lane)
{
    // TS*U*4 = 12800 bytes = 800 x 16B; 25 x 16B per lane, stride 512B.
    uint32_t d = (uint32_t)__cvta_generic_to_shared(dst_sh) + lane * 16;
    const char* s = reinterpret_cast<const char*>(src_g) + lane * 16;
#pragma unroll
    for (int i = 0; i < 25; i++) {
        asm volatile("cp.async.ca.shared.global [%0], [%1], 16;\n"
                     :: "r"(d + i * 512), "l"(s + i * 512));
    }
    asm volatile("cp.async.commit_group;\n");
}

__global__ __launch_bounds__(32) void alpha_kernel()
{
    const int b    = blockIdx.x;
    const int lane = threadIdx.x;

    __shared__ float2 lut[LUTN];
    __shared__ float  buf[2][BUFN];

    // Build the slope/intercept LUT for f(d) = log1p(exp(-d)), d in [0,16)
    for (int k = lane; k < LUTN; k += 32) {
        float x0 = (float)k / LUT_SCALE;
        float x1 = (float)(k + 1) / LUT_SCALE;
        float f0 = log1pf(__expf(-x0));
        float f1 = log1pf(__expf(-x1));
        float slope = (f1 - f0) * LUT_SCALE;
        lut[k] = make_float2(f0 - slope * x0, slope);   // f(d) ~= c.x + c.y*d
    }
    // Init the pad tails once: cp.async only ever writes [0, TS*U), so this
    // persists across all chunk reuses. Keeps the u>=200 overreads defined.
    buf[0][TS * U + lane] = 0.f;
    buf[1][TS * U + lane] = 0.f;

    const float* gl = g_lpt + (size_t)b * T * U;

    // Prologue: stage chunks 0 and 1
    cp_chunk(buf[0], gl, lane);
    cp_chunk(buf[1], gl + (size_t)TS * U, lane);

    float a[7];
#pragma unroll
    for (int j = 0; j < 7; j++) a[j] = NEGF;

    for (int c = 0; c < NCH; c++) {
        asm volatile("cp.async.wait_group 1;\n" ::: "memory");
        __syncwarp();

        const float* bp = buf[c & 1];
        int tr0 = 0;
        if (c == 0) {
            if (lane == 0) a[0] = bp[0];   // alpha[0,0] = lpt[0,0]
            tr0 = 1;
        }

        for (int trel = tr0; trel < TS; trel++) {
            const float* prow = bp + trel * U;
            // boundary: lane l needs lane l-1's OLD a[6]
            float left = __shfl_up_sync(0xffffffffu, a[6], 1);
            if (lane == 0) left = NEGF;

            float prev = left;
#pragma unroll
            for (int j = 0; j < 7; j++) {
                const float p   = prow[lane * 7 + j];  // LDS (staged), conflict-free
                const float old = a[j];
                const float m = fmaxf(old, prev);
                const float d = fminf(fabsf(old - prev), 15.9f);
                const int   k = (int)(d * LUT_SCALE);
                const float2 cf = lut[k];
                a[j] = p + m + fmaf(cf.y, d, cf.x);
                prev = old;
            }
        }

        __syncwarp();                                  // all lanes done reading buf[c&1]
        if (c + 2 < NCH) {
            cp_chunk(buf[c & 1], gl + (size_t)(c + 2) * TS * U, lane);
        } else {
            asm volatile("cp.async.commit_group;\n");  // keep group-count invariant
        }
    }

    if (lane == 28) g_partial[b] = a[3];               // u = 28*7 + 3 = 199
}

// ---------------------------------------------------------------------------
// Kernel 3: deterministic final reduction.
// ---------------------------------------------------------------------------
__global__ void finalize_kernel(float* __restrict__ out)
{
    float s = 0.f;
#pragma unroll
    for (int b = 0; b < B; b++) s += g_partial[b];
    out[0] = -s / (float)B;
}

extern "C" void kernel_launch(void* const* d_in, const int* in_sizes, int n_in,
                              void* d_out, int out_size)
{
    const float* x   = (const float*)d_in[0];   // [B, T, C] fp32
    const int*   tgt = (const int*)d_in[1];     // [B, U] int32
    float*       out = (float*)d_out;           // scalar fp32

    lse_gather_kernel<<<B * T, 256>>>(x, tgt);
    alpha_kernel<<<B, 32>>>();
    finalize_kernel<<<1, 1>>>(out);
}

// round 6
// speedup vs baseline: 3.4994x; 1.2043x over previous
#include <cuda_runtime.h>
#include <cstddef>
#include <cstdint>

// Problem shape (fixed by the dataset)
constexpr int B = 8;
constexpr int T = 2048;
constexpr int C = 4096;
constexpr int U = 200;
constexpr int UP = 256;              // padded per-frame stride (zero-filled tail)

// Scratch (no cudaMalloc allowed): P = exp(lpt) per (b,t,u), zero-padded
__device__ float g_p[(size_t)B * T * UP];    // 16.8 MB
__device__ float g_partial[B];

// ---------------------------------------------------------------------------
// Kernel 1: per-(b,t) row log-sum-exp + target gather, now emitting
// P = exp(x[tgt] - lse) directly (linear-domain probabilities).
// Measured at DRAM roofline (47.6us, 72% DRAM) — structure unchanged.
// ---------------------------------------------------------------------------
__global__ __launch_bounds__(256) void lse_gather_kernel(
    const float* __restrict__ x, const int* __restrict__ tgt)
{
    const int row = blockIdx.x;          // b*T + t
    const int b   = row >> 11;           // T = 2048
    const int tid = threadIdx.x;

    __shared__ float sh[C];
    __shared__ float red[8];
    __shared__ float s_bcast;

    const float4* r4 = reinterpret_cast<const float4*>(x) + (size_t)row * (C / 4);

    float4 v[4];
    float mx = -3.402823466e38f;
#pragma unroll
    for (int i = 0; i < 4; i++) {
        v[i] = r4[tid + i * 256];
        reinterpret_cast<float4*>(sh)[tid + i * 256] = v[i];
        mx = fmaxf(mx, fmaxf(fmaxf(v[i].x, v[i].y), fmaxf(v[i].z, v[i].w)));
    }

#pragma unroll
    for (int o = 16; o; o >>= 1) mx = fmaxf(mx, __shfl_xor_sync(0xffffffffu, mx, o));
    if ((tid & 31) == 0) red[tid >> 5] = mx;
    __syncthreads();
    if (tid == 0) {
        float m = red[0];
#pragma unroll
        for (int w = 1; w < 8; w++) m = fmaxf(m, red[w]);
        s_bcast = m;
    }
    __syncthreads();
    mx = s_bcast;

    float s = 0.f;
#pragma unroll
    for (int i = 0; i < 4; i++) {
        s += __expf(v[i].x - mx) + __expf(v[i].y - mx)
           + __expf(v[i].z - mx) + __expf(v[i].w - mx);
    }
#pragma unroll
    for (int o = 16; o; o >>= 1) s += __shfl_xor_sync(0xffffffffu, s, o);
    __syncthreads();
    if ((tid & 31) == 0) red[tid >> 5] = s;
    __syncthreads();
    if (tid == 0) {
        float t = 0.f;
#pragma unroll
        for (int w = 0; w < 8; w++) t += red[w];
        s_bcast = mx + __logf(t);
    }
    __syncthreads();
    const float lse = s_bcast;

    // Emit P = exp(lpt); pad columns [U,UP) are exact zeros (= -inf logically)
    if (tid < U) {
        const int c = tgt[b * U + tid] & (C - 1);
        g_p[(size_t)row * UP + tid] = __expf(sh[c] - lse);
    } else {
        g_p[(size_t)row * UP + tid] = 0.f;
    }
}

// ---------------------------------------------------------------------------
// Kernel 2 v3: single-warp-per-batch LINEAR-DOMAIN alpha recursion.
//   A[u] <- (A[u] + A[u-1]) * P[u]   (probability space)
//   - lane owns 8 contiguous u columns (32*8 = 256 = UP); u>=200 has P=0 so
//     those cells stay exactly 0 forever
//   - per-lane scale c, renormalized every 4 steps (lane max -> 1);
//     cross-lane boundary value adjusted by f = exp(c_left - c), updated only
//     at renorms; inactive (all-zero) lanes sync their scale to the left lane
//   - P staged in 16-step chunks, triple-buffered cp.async (prefetch 2 chunks
//     ~= 1200 cyc ahead of use)
// Serial chain per step: FADD+FMUL = 8 cyc (vs ~70 for the log-domain LUT).
// ---------------------------------------------------------------------------
constexpr int TS    = 16;            // time steps per staged chunk
constexpr int NCH   = T / TS;        // 128 chunks
constexpr int CHUNK = TS * UP;       // 4096 floats = 16 KB

__device__ __forceinline__ void cp_chunk(float* dst_sh, const float* src_g, int lane)
{
    // 16 KB = 1024 x 16B; 32 x 16B per lane, stride 512B
    uint32_t d = (uint32_t)__cvta_generic_to_shared(dst_sh) + lane * 16;
    const char* s = reinterpret_cast<const char*>(src_g) + lane * 16;
#pragma unroll
    for (int i = 0; i < 32; i++) {
        asm volatile("cp.async.ca.shared.global [%0], [%1], 16;\n"
                     :: "r"(d + i * 512), "l"(s + i * 512));
    }
    asm volatile("cp.async.commit_group;\n");
}

__global__ __launch_bounds__(32) void alpha_kernel()
{
    const int b    = blockIdx.x;
    const int lane = threadIdx.x;

    __shared__ alignas(16) float buf[3][CHUNK];

    const float* gp = g_p + (size_t)b * T * UP;

    // Prologue: stage chunks 0, 1, 2
    cp_chunk(buf[0], gp, lane);
    cp_chunk(buf[1], gp + CHUNK, lane);
    cp_chunk(buf[2], gp + 2 * (size_t)CHUNK, lane);

    float A[8];
#pragma unroll
    for (int j = 0; j < 8; j++) A[j] = 0.f;
    float csc = 0.f;                 // per-lane log-scale: alpha = log(A) + csc
    float f   = 1.f;                 // exp(c_left - c), refreshed at renorms

    for (int ch = 0; ch < NCH; ch++) {
        asm volatile("cp.async.wait_group 2;\n" ::: "memory");
        __syncthreads();             // visibility of all lanes' cp.async writes

        const float* bp = buf[ch % 3];
        int tr0 = 0;
        if (ch == 0) {
            if (lane == 0) A[0] = bp[0];   // alpha[0,0]: A = P[0,0], csc = 0
            tr0 = 1;
        }

        for (int tr = tr0; tr < TS; tr++) {
            const float4* pr = reinterpret_cast<const float4*>(bp + tr * UP) + lane * 2;
            const float4 pa = pr[0];
            const float4 pb = pr[1];
            float p[8] = {pa.x, pa.y, pa.z, pa.w, pb.x, pb.y, pb.z, pb.w};

            float left = __shfl_up_sync(0xffffffffu, A[7], 1);
            float prev = (lane == 0) ? 0.f : left * f;

#pragma unroll
            for (int j = 0; j < 8; j++) {
                const float nv = (A[j] + prev) * p[j];
                prev = A[j];
                A[j] = nv;
            }

            if ((tr & 3) == 3) {
                // per-lane renormalization (every 4 steps)
                float m = A[0];
#pragma unroll
                for (int j = 1; j < 8; j++) m = fmaxf(m, A[j]);
                const float me  = fmaxf(m, 1e-30f);
                const float inv = __fdividef(1.f, me);
                float cn = csc + __logf(me);
                const float cl = __shfl_up_sync(0xffffffffu, cn, 1);
                if (m < 1e-30f && lane > 0) cn = cl;   // inactive: adopt left scale
#pragma unroll
                for (int j = 0; j < 8; j++) A[j] *= inv;
                f   = (lane == 0) ? 1.f : __expf(cl - cn);
                csc = cn;
            }
        }

        __syncthreads();             // all lanes done reading buf[ch%3]
        if (ch + 3 < NCH) {
            cp_chunk(buf[ch % 3], gp + (size_t)(ch + 3) * CHUNK, lane);
        } else {
            asm volatile("cp.async.commit_group;\n");  // keep group-count invariant
        }
    }

    // u = 199 = lane 24, cell 7
    if (lane == 24) g_partial[b] = __logf(A[7]) + csc;
}

// ---------------------------------------------------------------------------
// Kernel 3: deterministic final reduction.
// ---------------------------------------------------------------------------
__global__ void finalize_kernel(float* __restrict__ out)
{
    float s = 0.f;
#pragma unroll
    for (int b = 0; b < B; b++) s += g_partial[b];
    out[0] = -s / (float)B;
}

extern "C" void kernel_launch(void* const* d_in, const int* in_sizes, int n_in,
                              void* d_out, int out_size)
{
    const float* x   = (const float*)d_in[0];   // [B, T, C] fp32
    const int*   tgt = (const int*)d_in[1];     // [B, U] int32
    float*       out = (float*)d_out;           // scalar fp32

    lse_gather_kernel<<<B * T, 256>>>(x, tgt);
    alpha_kernel<<<B, 32>>>();
    finalize_kernel<<<1, 1>>>(out);
}

// round 8
// speedup vs baseline: 6.3451x; 1.8132x over previous
#include <cuda_runtime.h>
#include <cstddef>
#include <cstdint>

// Problem shape (fixed by the dataset)
constexpr int B = 8;
constexpr int T = 2048;
constexpr int C = 4096;
constexpr int U = 200;
constexpr int UP = 256;              // padded per-frame stride (zero-filled tail)

// Scratch (no cudaMalloc allowed): P = exp(lpt) per (b,t,u), zero-padded
__device__ float g_p[(size_t)B * T * UP];    // 16.8 MB
__device__ float g_partial[B];

// ---------------------------------------------------------------------------
// Kernel 1: per-(b,t) row log-sum-exp + target gather, emitting P = exp(lpt).
// Row t=0 emits P only at u=0 (zeros elsewhere) so the alpha recursion can
// treat t=0 as a uniform step from the A[0]=1 seed state.
// Measured at DRAM roofline (47us, 73% DRAM) — structure unchanged.
// ---------------------------------------------------------------------------
__global__ __launch_bounds__(256) void lse_gather_kernel(
    const float* __restrict__ x, const int* __restrict__ tgt)
{
    const int row = blockIdx.x;          // b*T + t
    const int b   = row >> 11;           // T = 2048
    const int t   = row & (T - 1);
    const int tid = threadIdx.x;

    __shared__ float sh[C];
    __shared__ float red[8];
    __shared__ float s_bcast;

    const float4* r4 = reinterpret_cast<const float4*>(x) + (size_t)row * (C / 4);

    float4 v[4];
    float mx = -3.402823466e38f;
#pragma unroll
    for (int i = 0; i < 4; i++) {
        v[i] = r4[tid + i * 256];
        reinterpret_cast<float4*>(sh)[tid + i * 256] = v[i];
        mx = fmaxf(mx, fmaxf(fmaxf(v[i].x, v[i].y), fmaxf(v[i].z, v[i].w)));
    }

#pragma unroll
    for (int o = 16; o; o >>= 1) mx = fmaxf(mx, __shfl_xor_sync(0xffffffffu, mx, o));
    if ((tid & 31) == 0) red[tid >> 5] = mx;
    __syncthreads();
    if (tid == 0) {
        float m = red[0];
#pragma unroll
        for (int w = 1; w < 8; w++) m = fmaxf(m, red[w]);
        s_bcast = m;
    }
    __syncthreads();
    mx = s_bcast;

    float s = 0.f;
#pragma unroll
    for (int i = 0; i < 4; i++) {
        s += __expf(v[i].x - mx) + __expf(v[i].y - mx)
           + __expf(v[i].z - mx) + __expf(v[i].w - mx);
    }
#pragma unroll
    for (int o = 16; o; o >>= 1) s += __shfl_xor_sync(0xffffffffu, s, o);
    __syncthreads();
    if ((tid & 31) == 0) red[tid >> 5] = s;
    __syncthreads();
    if (tid == 0) {
        float tt = 0.f;
#pragma unroll
        for (int w = 0; w < 8; w++) tt += red[w];
        s_bcast = mx + __logf(tt);
    }
    __syncthreads();
    const float lse = s_bcast;

    // P = exp(lpt); pad columns and (t==0, u>0) are exact zeros
    if (tid < U) {
        const int c = tgt[b * U + tid] & (C - 1);
        const float p = __expf(sh[c] - lse);
        g_p[(size_t)row * UP + tid] = (t == 0 && tid > 0) ? 0.f : p;
    } else {
        g_p[(size_t)row * UP + tid] = 0.f;
    }
}

// ---------------------------------------------------------------------------
// Kernel 2 v4: warp-specialized linear-domain alpha recursion.
//   warp 0 (compute): lane owns 8 u-columns; A[u] <- (A[u]+A[u-1])*P[u].
//     - fully-unrolled constant 16-step inner loop (latencies overlapped)
//     - integer-exponent renorm every 4 steps (exact 2^k scaling, alu-pipe,
//       no MUFU on the critical path)
//   warp 1 (copy): triple-buffered cp.async staging of P, 16-step chunks.
// Seed state: A[0]=1 on lane 0 (plus zeroed P[0,u>0]) makes t=0 a normal step.
// ---------------------------------------------------------------------------
constexpr int TS    = 16;            // time steps per staged chunk
constexpr int NCH   = T / TS;        // 128 chunks
constexpr int CHUNK = TS * UP;       // 4096 floats = 16 KB

__device__ __forceinline__ void cp_chunk(float* dst_sh, const float* src_g, int lane)
{
    // 16 KB = 1024 x 16B; 32 x 16B per lane, stride 512B
    uint32_t d = (uint32_t)__cvta_generic_to_shared(dst_sh) + lane * 16;
    const char* s = reinterpret_cast<const char*>(src_g) + lane * 16;
#pragma unroll
    for (int i = 0; i < 32; i++) {
        asm volatile("cp.async.ca.shared.global [%0], [%1], 16;\n"
                     :: "r"(d + i * 512), "l"(s + i * 512));
    }
    asm volatile("cp.async.commit_group;\n");
}

__global__ __launch_bounds__(64) void alpha_kernel()
{
    const int b    = blockIdx.x;
    const int tid  = threadIdx.x;
    const int lane = tid & 31;
    const int wid  = tid >> 5;

    __shared__ alignas(16) float buf[3][CHUNK];

    const float* gp = g_p + (size_t)b * T * UP;

    if (wid == 1) {
        // ---- copy warp ----
        cp_chunk(buf[0], gp, lane);
        cp_chunk(buf[1], gp + CHUNK, lane);
        cp_chunk(buf[2], gp + 2 * (size_t)CHUNK, lane);
        for (int ch = 0; ch < NCH; ch++) {
            asm volatile("cp.async.wait_group 2;\n" ::: "memory");
            __syncthreads();                     // A: chunk ch is ready
            __syncthreads();                     // B: compute released buf[ch%3]
            if (ch + 3 < NCH)
                cp_chunk(buf[ch % 3], gp + (size_t)(ch + 3) * CHUNK, lane);
            else
                asm volatile("cp.async.commit_group;\n");
        }
        return;
    }

    // ---- compute warp ----
    float A[8];
#pragma unroll
    for (int j = 0; j < 8; j++) A[j] = 0.f;
    if (lane == 0) A[0] = 1.f;       // seed: with P[0,u>0]=0 this makes t=0 uniform
    int   E = 0;                      // per-lane scale: true_alpha = A * 2^E
    float f = 1.f;                    // 2^(E_left - E), refreshed at renorms

    for (int ch = 0; ch < NCH; ch++) {
        __syncthreads();              // A: chunk data ready
        const float* bp = buf[ch % 3];

#pragma unroll
        for (int tr = 0; tr < TS; tr++) {
            const float4* pr = reinterpret_cast<const float4*>(bp + tr * UP) + lane * 2;
            const float4 pa = pr[0];
            const float4 pb = pr[1];
            const float p[8] = {pa.x, pa.y, pa.z, pa.w, pb.x, pb.y, pb.z, pb.w};

            const float left = __shfl_up_sync(0xffffffffu, A[7], 1);
            float prev = (lane == 0) ? 0.f : left * f;

#pragma unroll
            for (int j = 0; j < 8; j++) {
                const float nv = (A[j] + prev) * p[j];
                prev = A[j];
                A[j] = nv;
            }

            if ((tr & 3) == 3) {
                // integer-exponent renorm: exact, MUFU-free, alu-pipe
                float m = fmaxf(fmaxf(fmaxf(A[0], A[1]), fmaxf(A[2], A[3])),
                                fmaxf(fmaxf(A[4], A[5]), fmaxf(A[6], A[7])));
                const int e  = (int)(__float_as_uint(m) >> 23) - 127;
                int cn = E + e;
                const int cl = __shfl_up_sync(0xffffffffu, cn, 1);
                if (m == 0.f && lane > 0) cn = cl;   // inactive: adopt left scale
                const float inv = __uint_as_float((uint32_t)(127 - e) << 23);
#pragma unroll
                for (int j = 0; j < 8; j++) A[j] *= inv;
                E = cn;
                int d = cl - E;
                d = (d > 120) ? 120 : d;             // no overflow to inf
                f = (d < -126) ? 0.f
                               : __uint_as_float((uint32_t)(127 + d) << 23);
                if (lane == 0) f = 1.f;              // unused (prev forced 0)
            }
        }

        __syncthreads();              // B: done reading buf[ch%3]
    }

    // u = 199 = lane 24, cell 7; last renorm was at t=2047, so (A,E) consistent
    if (lane == 24)
        g_partial[b] = (float)(log((double)A[7]) + (double)E * 0.6931471805599453);
}

// ---------------------------------------------------------------------------
// Kernel 3: deterministic final reduction.
// ---------------------------------------------------------------------------
__global__ void finalize_kernel(float* __restrict__ out)
{
    float s = 0.f;
#pragma unroll
    for (int b = 0; b < B; b++) s += g_partial[b];
    out[0] = -s / (float)B;
}

extern "C" void kernel_launch(void* const* d_in, const int* in_sizes, int n_in,
                              void* d_out, int out_size)
{
    const float* x   = (const float*)d_in[0];   // [B, T, C] fp32
    const int*   tgt = (const int*)d_in[1];     // [B, U] int32
    float*       out = (float*)d_out;           // scalar fp32

    lse_gather_kernel<<<B * T, 256>>>(x, tgt);
    alpha_kernel<<<B, 64>>>();
    finalize_kernel<<<1, 1>>>(out);
}